// round 16
// baseline (speedup 1.0000x reference)
#include <cuda_runtime.h>
#include <cuda_bf16.h>
#include <math.h>
#include <stdint.h>

#define Bb   64
#define Nn   1024
#define DIN  32
#define DOUT 64
#define CIN  96
#define KSUP 3
#define EDm  16
#define OG   128
#define OU   64
#define KI   288

__device__ float g_bg [(size_t)Nn * OG];
__device__ float g_bu [(size_t)Nn * OU];
__device__ float g_Lt [(size_t)Nn * Nn];
__device__ float g_Amats[(size_t)5 * Nn * Nn];   // [L, S2, cheb0, cheb1, cheb2]
__device__ float g_XG [(size_t)Bb * Nn * KI];
__device__ float g_Ucm [(size_t)Bb * CIN * Nn];
__device__ float g_X0T[(size_t)Bb * OG * Nn];
__device__ float g_XG1[(size_t)Bb * Nn * 3 * OG];
__device__ float g_G0 [(size_t)Bb * Nn * OG];
__device__ float g_G1 [(size_t)Bb * Nn * OG];
__device__ float g_Rb [(size_t)Bb * Nn * DOUT];
__device__ float g_Yp [2 * Bb * 8 * OG];
__device__ float g_s0 [Bb];
__device__ float g_s1 [Bb];
__device__ float g_iwTg [CIN * OG];
__device__ float g_Wcomb[OG * KI];
__device__ float g_bias2[Nn * OG];
__device__ float g_rs [KSUP * Nn];
__device__ float g_vv [KSUP * OG];
__device__ uint32_t g_WtgH[(size_t)Nn * OG * (KI / 2)], g_WtgL[(size_t)Nn * OG * (KI / 2)];
__device__ uint32_t g_WtuH[(size_t)Nn * OU * (KI / 2)], g_WtuL[(size_t)Nn * OU * (KI / 2)];

// ---------- mma / ldmatrix helpers ----------
static __device__ __forceinline__ void mma16(float* d, const uint32_t* a,
                                             uint32_t b0, uint32_t b1) {
    asm volatile(
        "mma.sync.aligned.m16n8k16.row.col.f32.bf16.bf16.f32 "
        "{%0,%1,%2,%3}, {%4,%5,%6,%7}, {%8,%9}, {%0,%1,%2,%3};"
        : "+f"(d[0]), "+f"(d[1]), "+f"(d[2]), "+f"(d[3])
        : "r"(a[0]), "r"(a[1]), "r"(a[2]), "r"(a[3]), "r"(b0), "r"(b1));
}
#define LDMX4(r, ad) \
    asm volatile("ldmatrix.sync.aligned.m8n8.x4.shared.b16 {%0,%1,%2,%3}, [%4];" \
        : "=r"((r)[0]), "=r"((r)[1]), "=r"((r)[2]), "=r"((r)[3]) : "r"(ad))
#define LDMX2(r0, r1, ad) \
    asm volatile("ldmatrix.sync.aligned.m8n8.x2.shared.b16 {%0,%1}, [%2];" \
        : "=r"(r0), "=r"(r1) : "r"(ad))

static __device__ __forceinline__ uint32_t packbf(float x, float y) {
    __nv_bfloat162 h = __floats2bfloat162_rn(x, y);
    return *reinterpret_cast<uint32_t*>(&h);
}
static __device__ __forceinline__ void split2(float a, float b, uint32_t& hi, uint32_t& lo) {
    __nv_bfloat16 ha = __float2bfloat16_rn(a), hb = __float2bfloat16_rn(b);
    __nv_bfloat162 p; p.x = ha; p.y = hb;
    hi = *reinterpret_cast<uint32_t*>(&p);
    lo = packbf(a - __bfloat162float(ha), b - __bfloat162float(hb));
}
static __device__ __forceinline__ void split4(float4 v, uint2& hi, uint2& lo) {
    split2(v.x, v.y, hi.x, lo.x);
    split2(v.z, v.w, hi.y, lo.y);
}

#define RSTR 20

// ---------- bf16x3 GEMM (R15 winner; now 2 CTAs/SM) ----------
template <int NT>
__global__ __launch_bounds__(256, 2) void mma_gemm(
    const float* __restrict__ A, int lda, long sA2,
    const float* __restrict__ Bm, int ldb,
    float* __restrict__ C, float* __restrict__ Calt, int zc, long cSel,
    int ldc, long sCb, int scatDiv,
    int K, const float* __restrict__ bias, const float* __restrict__ bias2, int ldb2,
    float alpha, int minusI, float* __restrict__ TO, long sTOb)
{
    constexpr int NTILES = NT / 16;
    constexpr int NB = NT / 32;
    constexpr int AROWS_U32 = 128 * RSTR;
    constexpr int BROWS_U32 = NT * RSTR;
    constexpr int STG = 2 * AROWS_U32 + 2 * BROWS_U32;

    extern __shared__ uint32_t dsm[];

    const int z = blockIdx.z;
    A += (long)z * sA2;
    float* Cbase = (z < zc) ? C + (long)z * cSel : Calt + (long)(z - zc) * cSel;

    const int m0 = blockIdx.y * 128, n0 = blockIdx.x * NT;
    const int tid = threadIdx.x, wid = tid >> 5, lid = tid & 31;
    const int g = lid >> 2, t = lid & 3;
    const int wm = (wid & 3) * 32, wn = (wid >> 2) * (NT / 2);

    const float* Ag = A + (long)m0 * lda;
    const float* Bg = Bm + (long)n0 * ldb;

    float acc[2][NTILES][4];
    #pragma unroll
    for (int i = 0; i < 2; i++)
        #pragma unroll
        for (int j = 0; j < NTILES; j++)
            #pragma unroll
            for (int q = 0; q < 4; q++) acc[i][j][q] = 0.f;

    const int nch = K >> 5;
    float4 pA[4], pB[NB];

    const uint32_t smem0 = (uint32_t)__cvta_generic_to_shared(dsm);
    const uint32_t laneAoff = (((wm + (lid & 15)) * RSTR + ((lid & 16) ? 4 : 0)) << 2);
    const uint32_t laneBoff = (((2 * AROWS_U32) + (wn + (lid & 7)) * RSTR + ((lid & 8) ? 4 : 0)) << 2);

    #pragma unroll
    for (int i = 0; i < 4; i++) {
        int f = i * 256 + tid;
        pA[i] = *(const float4*)(Ag + (long)(f >> 3) * lda + ((f & 7) << 2));
    }
    #pragma unroll
    for (int i = 0; i < NB; i++) {
        int f = i * 256 + tid;
        pB[i] = *(const float4*)(Bg + (long)(f >> 3) * ldb + ((f & 7) << 2));
    }
    {
        uint32_t* Ah = dsm;                 uint32_t* Al = dsm + AROWS_U32;
        uint32_t* Bh = dsm + 2 * AROWS_U32; uint32_t* Bl = Bh + BROWS_U32;
        #pragma unroll
        for (int i = 0; i < 4; i++) {
            int f = i * 256 + tid, row = f >> 3, q = f & 7;
            uint2 hi, lo; split4(pA[i], hi, lo);
            *(uint2*)(Ah + row * RSTR + 2 * q) = hi;
            *(uint2*)(Al + row * RSTR + 2 * q) = lo;
        }
        #pragma unroll
        for (int i = 0; i < NB; i++) {
            int f = i * 256 + tid, row = f >> 3, q = f & 7;
            uint2 hi, lo; split4(pB[i], hi, lo);
            *(uint2*)(Bh + row * RSTR + 2 * q) = hi;
            *(uint2*)(Bl + row * RSTR + 2 * q) = lo;
        }
    }
    __syncthreads();

    for (int c = 0; c < nch; c++) {
        if (c + 1 < nch) {
            const int k0 = (c + 1) << 5;
            #pragma unroll
            for (int i = 0; i < 4; i++) {
                int f = i * 256 + tid;
                pA[i] = *(const float4*)(Ag + (long)(f >> 3) * lda + k0 + ((f & 7) << 2));
            }
            #pragma unroll
            for (int i = 0; i < NB; i++) {
                int f = i * 256 + tid;
                pB[i] = *(const float4*)(Bg + (long)(f >> 3) * ldb + k0 + ((f & 7) << 2));
            }
        }
        {
            const uint32_t stB = smem0 + (c & 1) * (STG << 2);
            const uint32_t aA = stB + laneAoff;
            const uint32_t aB = stB + laneBoff;
            #pragma unroll
            for (int s = 0; s < 2; s++) {
                uint32_t ah[2][4], al[2][4];
                #pragma unroll
                for (int mt = 0; mt < 2; mt++) {
                    uint32_t ad = aA + mt * (16 * RSTR * 4) + s * 32;
                    LDMX4(ah[mt], ad);
                    LDMX4(al[mt], ad + AROWS_U32 * 4);
                }
                #pragma unroll
                for (int nt = 0; nt < NTILES; nt++) {
                    uint32_t bd = aB + nt * (8 * RSTR * 4) + s * 32;
                    uint32_t bh0, bh1, bl0, bl1;
                    LDMX2(bh0, bh1, bd);
                    LDMX2(bl0, bl1, bd + BROWS_U32 * 4);
                    #pragma unroll
                    for (int mt = 0; mt < 2; mt++) {
                        mma16(acc[mt][nt], ah[mt], bh0, bh1);
                        mma16(acc[mt][nt], al[mt], bh0, bh1);
                        mma16(acc[mt][nt], ah[mt], bl0, bl1);
                    }
                }
            }
        }
        if (c + 1 < nch) {
            uint32_t* base = dsm + ((c + 1) & 1) * STG;
            uint32_t* Ah = base;                 uint32_t* Al = base + AROWS_U32;
            uint32_t* Bh = base + 2 * AROWS_U32; uint32_t* Bl = Bh + BROWS_U32;
            #pragma unroll
            for (int i = 0; i < 4; i++) {
                int f = i * 256 + tid, row = f >> 3, q = f & 7;
                uint2 hi, lo; split4(pA[i], hi, lo);
                *(uint2*)(Ah + row * RSTR + 2 * q) = hi;
                *(uint2*)(Al + row * RSTR + 2 * q) = lo;
            }
            #pragma unroll
            for (int i = 0; i < NB; i++) {
                int f = i * 256 + tid, row = f >> 3, q = f & 7;
                uint2 hi, lo; split4(pB[i], hi, lo);
                *(uint2*)(Bh + row * RSTR + 2 * q) = hi;
                *(uint2*)(Bl + row * RSTR + 2 * q) = lo;
            }
            __syncthreads();
        }
    }

    #pragma unroll
    for (int mt = 0; mt < 2; mt++) {
        int r0 = m0 + wm + mt * 16 + g;
        #pragma unroll
        for (int nt = 0; nt < NTILES; nt++) {
            int col = n0 + wn + nt * 8 + t * 2;
            float b0 = 0.f, b1 = 0.f;
            if (bias) { b0 = __ldg(&bias[col]); b1 = __ldg(&bias[col + 1]); }
            float d0 = acc[mt][nt][0] * alpha + b0;
            float d1 = acc[mt][nt][1] * alpha + b1;
            float d2 = acc[mt][nt][2] * alpha + b0;
            float d3 = acc[mt][nt][3] * alpha + b1;
            if (bias2) {
                const float* p0 = bias2 + (long)(r0 & 1023) * ldb2 + col;
                const float* p1 = bias2 + (long)((r0 + 8) & 1023) * ldb2 + col;
                d0 += p0[0]; d1 += p0[1]; d2 += p1[0]; d3 += p1[1];
            }
            if (minusI) {
                if (r0 == col)         d0 -= 1.0f;
                if (r0 == col + 1)     d1 -= 1.0f;
                if (r0 + 8 == col)     d2 -= 1.0f;
                if (r0 + 8 == col + 1) d3 -= 1.0f;
            }
            if (TO) {
                int bb = r0 >> 10, rr = r0 & 1023;
                float* p = TO + (long)bb * sTOb + (long)col * Nn + rr;
                p[0] = d0; p[Nn] = d1; p[8] = d2; p[Nn + 8] = d3;
            } else if (scatDiv) {
                int b = col / scatDiv, cc = col - b * scatDiv;
                float* p = Cbase + (long)b * sCb + (long)r0 * ldc + cc;
                *(float2*)p = make_float2(d0, d1);
                *(float2*)(p + 8L * ldc) = make_float2(d2, d3);
            } else {
                *(float2*)(Cbase + (long)r0 * ldc + col)       = make_float2(d0, d1);
                *(float2*)(Cbase + (long)(r0 + 8) * ldc + col) = make_float2(d2, d3);
            }
        }
    }
}

// ---------- fused emb@pool -> transposed split weights ----------
template <int O>
__global__ __launch_bounds__(256) void emb_wsplit(
    const float* __restrict__ emb, const float* __restrict__ pool,
    uint32_t* __restrict__ WtH, uint32_t* __restrict__ WtL)
{
    __shared__ float es[32][EDm];
    __shared__ float ps[EDm][16][32];
    const int tid = threadIdx.x;
    const int n0 = blockIdx.x * 32;
    const int ki0 = blockIdx.y * 16;
    const int o0 = blockIdx.z * 32;
    const int Ctot = KI * O;
    for (int i = tid; i < 32 * EDm; i += 256)
        es[i >> 4][i & 15] = emb[(n0 + (i >> 4)) * EDm + (i & 15)];
    for (int i = tid; i < EDm * 16 * 32; i += 256) {
        int o = i & 31, kil = (i >> 5) & 15, d = i >> 9;
        ps[d][kil][o] = pool[(long)d * Ctot + (long)(ki0 + kil) * O + o0 + o];
    }
    __syncthreads();
    const int kp = tid & 7, o = tid >> 3;
    float p0[EDm], p1[EDm];
    #pragma unroll
    for (int d = 0; d < EDm; d++) { p0[d] = ps[d][2 * kp][o]; p1[d] = ps[d][2 * kp + 1][o]; }
    const long base = (long)(o0 + o) * (KI / 2) + (ki0 >> 1) + kp;
    for (int n = 0; n < 32; n++) {
        float v0 = 0.f, v1 = 0.f;
        #pragma unroll
        for (int d = 0; d < EDm; d++) { float e = es[n][d]; v0 += e * p0[d]; v1 += e * p1[d]; }
        uint32_t h, l; split2(v0, v1, h, l);
        long off = (long)(n0 + n) * O * (KI / 2) + base;
        WtH[off] = h; WtL[off] = l;
    }
}

// ---------- per-node contraction (now 2 CTAs/SM) ----------
template <int O>
__global__ __launch_bounds__(256, 2) void pernode_mma(
    const float* __restrict__ XG, const uint32_t* __restrict__ WtH,
    const uint32_t* __restrict__ WtL, const float* __restrict__ bias,
    float* __restrict__ out)
{
    constexpr int NTILES = O / 32;
    constexpr int AR = 64 * RSTR;
    constexpr int BR = O * RSTR;
    __shared__ uint32_t psm[2 * AR + 2 * BR];

    const int n = blockIdx.x, tid = threadIdx.x, wid = tid >> 5, lid = tid & 31;
    const int g = lid >> 2, t = lid & 3;
    const int wm = (wid & 1) * 32, wn = (wid >> 1) * (O / 4);

    const uint32_t* Hn = WtH + (long)n * O * (KI / 2);
    const uint32_t* Ln = WtL + (long)n * O * (KI / 2);

    float acc[2][NTILES][4];
    #pragma unroll
    for (int i = 0; i < 2; i++)
        #pragma unroll
        for (int j = 0; j < NTILES; j++)
            #pragma unroll
            for (int q = 0; q < 4; q++) acc[i][j][q] = 0.f;

    const uint32_t smem0 = (uint32_t)__cvta_generic_to_shared(psm);
    const uint32_t laneAoff = (((wm + (lid & 15)) * RSTR + ((lid & 16) ? 4 : 0)) << 2);
    const uint32_t laneBoff = (((2 * AR) + (wn + (lid & 7)) * RSTR + ((lid & 8) ? 4 : 0)) << 2);

    uint32_t* Ah = psm;          uint32_t* Al = psm + AR;
    uint32_t* Bh = psm + 2 * AR; uint32_t* Bl = Bh + BR;

    for (int c = 0; c < KI / 32; c++) {
        const int k0 = c << 5;
        if (c) __syncthreads();
        #pragma unroll
        for (int i = 0; i < 2; i++) {
            int f = i * 256 + tid, row = f >> 3, q = f & 7;
            float4 v = *(const float4*)(XG + ((long)row * Nn + n) * KI + k0 + (q << 2));
            uint2 hi, lo; split4(v, hi, lo);
            *(uint2*)(Ah + row * RSTR + 2 * q) = hi;
            *(uint2*)(Al + row * RSTR + 2 * q) = lo;
        }
        #pragma unroll
        for (int i = 0; i < O / 64; i++) {
            int f = i * 256 + tid, row = f >> 2, qc = (f & 3) << 2;
            *(uint4*)(Bh + row * RSTR + qc) = *(const uint4*)(Hn + (long)row * (KI / 2) + (k0 >> 1) + qc);
            *(uint4*)(Bl + row * RSTR + qc) = *(const uint4*)(Ln + (long)row * (KI / 2) + (k0 >> 1) + qc);
        }
        __syncthreads();

        #pragma unroll
        for (int s = 0; s < 2; s++) {
            uint32_t ah[2][4], al[2][4];
            #pragma unroll
            for (int mt = 0; mt < 2; mt++) {
                uint32_t ad = smem0 + laneAoff + mt * (16 * RSTR * 4) + s * 32;
                LDMX4(ah[mt], ad);
                LDMX4(al[mt], ad + AR * 4);
            }
            #pragma unroll
            for (int nt = 0; nt < NTILES; nt++) {
                uint32_t bd = smem0 + laneBoff + nt * (8 * RSTR * 4) + s * 32;
                uint32_t bh0, bh1, bl0, bl1;
                LDMX2(bh0, bh1, bd);
                LDMX2(bl0, bl1, bd + BR * 4);
                #pragma unroll
                for (int mt = 0; mt < 2; mt++) {
                    mma16(acc[mt][nt], ah[mt], bh0, bh1);
                    mma16(acc[mt][nt], al[mt], bh0, bh1);
                    mma16(acc[mt][nt], ah[mt], bl0, bl1);
                }
            }
        }
    }

    #pragma unroll
    for (int mt = 0; mt < 2; mt++) {
        int b = wm + mt * 16 + g;
        #pragma unroll
        for (int nt = 0; nt < NTILES; nt++) {
            int col = wn + nt * 8 + t * 2;
            float b0 = bias[(long)n * O + col], b1 = bias[(long)n * O + col + 1];
            *(float2*)(out + ((long)b * Nn + n) * O + col) =
                make_float2(acc[mt][nt][0] + b0, acc[mt][nt][1] + b1);
            *(float2*)(out + ((long)(b + 8) * Nn + n) * O + col) =
                make_float2(acc[mt][nt][2] + b0, acc[mt][nt][3] + b1);
        }
    }
}

// ---------- small kernels ----------
static __device__ __forceinline__ float lrelu(float v) { return v >= 0.0f ? v : 0.01f * v; }
static __device__ __forceinline__ float sigmoidf(float v) { return 1.0f / (1.0f + expf(-v)); }

__global__ void bias_both(const float* __restrict__ emb,
                          const float* __restrict__ gpool, const float* __restrict__ upool,
                          float* __restrict__ bgo, float* __restrict__ buo)
{
    __shared__ float esm[32][EDm];
    const int tid = threadIdx.x;
    const int which = blockIdx.x;
    const int n0 = blockIdx.y * 32;
    const int C = which ? OU : OG;
    const float* pool = which ? upool : gpool;
    float* out = which ? buo : bgo;
    for (int i = tid; i < 32 * EDm; i += 256)
        esm[i >> 4][i & 15] = emb[(n0 + (i >> 4)) * EDm + (i & 15)];
    __syncthreads();
    if (tid >= C) return;
    float p[EDm];
    #pragma unroll
    for (int d = 0; d < EDm; d++) p[d] = pool[(long)d * C + tid];
    #pragma unroll 4
    for (int r = 0; r < 32; r++) {
        float acc = 0.f;
        #pragma unroll
        for (int d = 0; d < EDm; d++) acc += esm[r][d] * p[d];
        out[(long)(n0 + r) * C + tid] = acc;
    }
}

__global__ void transpose_batched(const float* __restrict__ in, long s_in, int ld_in,
                                  float* __restrict__ out, long s_out, int ld_out,
                                  int R, int Cc)
{
    __shared__ float tsm[32][33];
    in  += (long)blockIdx.z * s_in;
    out += (long)blockIdx.z * s_out;
    int r0 = blockIdx.x * 32, c0 = blockIdx.y * 32;
    int c = c0 + threadIdx.x;
    #pragma unroll
    for (int i = 0; i < 32; i += 8) {
        int rr = r0 + threadIdx.y + i;
        if (rr < R && c < Cc) tsm[threadIdx.y + i][threadIdx.x] = in[(long)rr * ld_in + c];
    }
    __syncthreads();
    int rr = r0 + threadIdx.x;
    #pragma unroll
    for (int i = 0; i < 32; i += 8) {
        int cc = c0 + threadIdx.y + i;
        if (cc < Cc && rr < R) out[(long)cc * ld_out + rr] = tsm[threadIdx.x][threadIdx.y + i];
    }
}

__global__ void build_ucm(const float* __restrict__ x, const float* __restrict__ st,
                          float* __restrict__ XG, float* __restrict__ Ucm)
{
    __shared__ float tsm[32][33];
    const int n0 = blockIdx.x * 32, c0 = blockIdx.y * 32, b = blockIdx.z;
    const int c = threadIdx.x;
    #pragma unroll
    for (int i = 0; i < 32; i += 8) {
        int n = n0 + threadIdx.y + i;
        long bn = (long)b * Nn + n;
        int gc = c0 + c;
        float v = (gc < DIN) ? x[bn * DIN + gc] : st[bn * DOUT + (gc - DIN)];
        tsm[threadIdx.y + i][c] = v;
        XG[bn * KI + gc] = v;
    }
    __syncthreads();
    const int n = n0 + threadIdx.x;
    #pragma unroll
    for (int i = 0; i < 32; i += 8) {
        int gc = c0 + threadIdx.y + i;
        Ucm[((long)b * CIN + gc) * Nn + n] = tsm[threadIdx.x][threadIdx.y + i];
    }
}

__global__ void gate_combine_t(const float* __restrict__ G0, const float* __restrict__ G1,
                               const float* __restrict__ s0, const float* __restrict__ s1,
                               const float* __restrict__ x, const float* __restrict__ st,
                               float* __restrict__ XG, float* __restrict__ Ucm,
                               float* __restrict__ Rb)
{
    __shared__ float tsm[32][33];
    const int n0 = blockIdx.x * 32, c0 = blockIdx.y * 32, b = blockIdx.z;
    const int c = threadIdx.x;
    const float a0 = s0[b], a1 = s1[b];
    #pragma unroll
    for (int i = 0; i < 32; i += 8) {
        int n = n0 + threadIdx.y + i;
        long bn = (long)b * Nn + n;
        int gc = c0 + c;
        float v;
        if (gc < DIN) {
            v = x[bn * DIN + gc];
        } else {
            int o = gc - DIN;
            float zi = lrelu(G0[bn * OG + o]) * a0 + lrelu(G1[bn * OG + o]) * a1;
            float ri = lrelu(G0[bn * OG + DOUT + o]) * a0 + lrelu(G1[bn * OG + DOUT + o]) * a1;
            Rb[bn * DOUT + o] = sigmoidf(ri);
            v = sigmoidf(zi) * st[bn * DOUT + o];
        }
        tsm[threadIdx.y + i][c] = v;
        XG[bn * KI + gc] = v;
    }
    __syncthreads();
    const int n = n0 + threadIdx.x;
    #pragma unroll
    for (int i = 0; i < 32; i += 8) {
        int gc = c0 + threadIdx.y + i;
        Ucm[((long)b * CIN + gc) * Nn + n] = tsm[threadIdx.x][threadIdx.y + i];
    }
}

__global__ void rowsum(const float* __restrict__ M, float* __restrict__ rs, int ncols)
{
    __shared__ float sm[256];
    const float* p = M + (long)blockIdx.x * ncols;
    float s = 0.f;
    for (int i = threadIdx.x; i < ncols; i += 256) s += p[i];
    sm[threadIdx.x] = s;
    __syncthreads();
    for (int o = 128; o; o >>= 1) {
        if (threadIdx.x < o) sm[threadIdx.x] += sm[threadIdx.x + o];
        __syncthreads();
    }
    if (!threadIdx.x) rs[blockIdx.x] = sm[0];
}

__global__ void vcomp(const float* __restrict__ gw, const float* __restrict__ ib,
                      float* __restrict__ vv)
{
    int k = blockIdx.x, o = threadIdx.x;
    float s = 0.f;
    for (int j = 0; j < OG; j++) s += gw[(long)o * (3 * OG) + k * OG + j] * ib[j];
    vv[k * OG + o] = s;
}

__global__ void mkbias2(const float* __restrict__ rs, const float* __restrict__ vv,
                        const float* __restrict__ gb, float* __restrict__ b2)
{
    int n = blockIdx.x, o = threadIdx.x;
    float s = gb[o];
    #pragma unroll
    for (int k = 0; k < KSUP; k++) s += rs[k * Nn + n] * vv[k * OG + o];
    b2[(long)n * OG + o] = s;
}

__global__ void colmean_part(const float* __restrict__ G0, const float* __restrict__ G1,
                             float* __restrict__ Yp, int C)
{
    const int b = blockIdx.x, ch = blockIdx.y, which = blockIdx.z;
    const int c = threadIdx.x;
    const float* p = (which ? G1 : G0) + ((long)b * Nn + ch * 128) * C + c;
    float a0 = 0.f, a1 = 0.f, a2 = 0.f, a3 = 0.f;
    #pragma unroll 4
    for (int n = 0; n < 128; n += 4) {
        a0 += lrelu(p[(long)n * C]);       a1 += lrelu(p[(long)(n + 1) * C]);
        a2 += lrelu(p[(long)(n + 2) * C]); a3 += lrelu(p[(long)(n + 3) * C]);
    }
    Yp[((long)(which * Bb + b) * 8 + ch) * C + c] = (a0 + a1) + (a2 + a3);
}

__global__ void att_fused(const float* __restrict__ Yp,
                          const float* __restrict__ w1a, const float* __restrict__ w2a,
                          const float* __restrict__ w1b, const float* __restrict__ w2b,
                          float* __restrict__ sa, float* __restrict__ sb, int C, int H)
{
    __shared__ float Y[OG];
    const int b = blockIdx.x, which = blockIdx.y;
    const int tid = threadIdx.x;
    if (tid < C) {
        const float* p = Yp + ((long)(which * Bb + b) * 8) * C + tid;
        float s = 0.f;
        #pragma unroll
        for (int ch = 0; ch < 8; ch++) s += p[ch * C];
        Y[tid] = s * (1.0f / (float)Nn);
    }
    __syncthreads();
    const float* w1 = which ? w1b : w1a;
    const float* w2 = which ? w2b : w2a;
    float h = 0.f;
    if (tid < H) {
        float acc = 0.f;
        for (int cc = 0; cc < C; cc++) acc += Y[cc] * w1[tid * C + cc];
        h = fmaxf(acc, 0.f) * w2[tid];
    }
    if (tid < 32) {
        #pragma unroll
        for (int off = 16; off; off >>= 1) h += __shfl_down_sync(0xffffffffu, h, off);
        if (tid == 0) (which ? sb : sa)[b] = sigmoidf(h);
    }
}

__global__ void final_combine(const float* __restrict__ G0u, const float* __restrict__ G1u,
                              const float* __restrict__ t0, const float* __restrict__ t1,
                              const float* __restrict__ Rb, const float* __restrict__ st,
                              float* __restrict__ out)
{
    long idx = (long)blockIdx.x * blockDim.x + threadIdx.x;
    if (idx >= (long)Bb * Nn * DOUT) return;
    long bn = idx / DOUT;
    int b = (int)(bn >> 10);
    float hc = tanhf(lrelu(G0u[idx]) * t0[b] + lrelu(G1u[idx]) * t1[b]);
    float r = Rb[idx];
    out[idx] = r * st[idx] + (1.0f - r) * hc;
}

// ---------- host ----------
static inline int gemm_smem(int NT) { return 2 * (2 * 128 * RSTR + 2 * NT * RSTR) * 4; }

struct GA {
    const float* A; int lda; long sA2;
    const float* B; int ldb;
    float* C; float* Calt = nullptr; int zc = 99; long cSel = 0;
    int ldc; long sCb = 0; int scatDiv = 0;
    int K; const float* bias = nullptr; const float* bias2 = nullptr; int ldb2 = 0;
    float alpha = 1.0f; int mI = 0;
    float* TO = nullptr; long sTOb = 0;
};
static inline void tc(int M, int N, int NT, int gz, const GA& a)
{
    dim3 grid(N / NT, M / 128, gz);
    int sm = gemm_smem(NT);
#define LNCH(T) \
    cudaFuncSetAttribute(mma_gemm<T>, cudaFuncAttributeMaxDynamicSharedMemorySize, sm); \
    mma_gemm<T><<<grid, 256, sm>>>(a.A, a.lda, a.sA2, a.B, a.ldb, \
        a.C, a.Calt, a.zc, a.cSel, a.ldc, a.sCb, a.scatDiv, \
        a.K, a.bias, a.bias2, a.ldb2, a.alpha, a.mI, a.TO, a.sTOb)
    switch (NT) {
    case 128: { LNCH(128); break; }
    case 96:  { LNCH(96);  break; }
    default:  { LNCH(64);  break; }
    }
#undef LNCH
}

extern "C" void kernel_launch(void* const* d_in, const int* in_sizes, int n_in,
                              void* d_out, int out_size)
{
    const float* x     = (const float*)d_in[0];
    const float* state = (const float*)d_in[1];
    const float* emb   = (const float*)d_in[2];
    const float* Lm    = (const float*)d_in[3];
    const float* cheb  = (const float*)d_in[4];
    const float* gwpool = (const float*)d_in[5];
    const float* gbpool = (const float*)d_in[6];
    const float* giw = (const float*)d_in[7];
    const float* gib = (const float*)d_in[8];
    const float* ggw = (const float*)d_in[9];
    const float* ggb = (const float*)d_in[10];
    const float* ga1w1 = (const float*)d_in[11];
    const float* ga1w2 = (const float*)d_in[12];
    const float* ga2w1 = (const float*)d_in[13];
    const float* ga2w2 = (const float*)d_in[14];
    const float* uwpool = (const float*)d_in[15];
    const float* ubpool = (const float*)d_in[16];
    const float* uiw = (const float*)d_in[17];
    const float* uib = (const float*)d_in[18];
    const float* ugw = (const float*)d_in[19];
    const float* ugb = (const float*)d_in[20];
    const float* ua1w1 = (const float*)d_in[21];
    const float* ua1w2 = (const float*)d_in[22];
    const float* ua2w1 = (const float*)d_in[23];
    const float* ua2w2 = (const float*)d_in[24];
    float* out = (float*)d_out;

    float *bg, *bu, *Lt, *Amats, *XG, *Ucm, *X0T, *XG1;
    float *G0, *G1, *Rb, *Yp, *s0, *s1;
    float *iwTg, *Wcomb, *bias2, *rs, *vv;
    uint32_t *WtgH, *WtgL, *WtuH, *WtuL;
    cudaGetSymbolAddress((void**)&bg, g_bg);     cudaGetSymbolAddress((void**)&bu, g_bu);
    cudaGetSymbolAddress((void**)&Lt, g_Lt);     cudaGetSymbolAddress((void**)&Amats, g_Amats);
    cudaGetSymbolAddress((void**)&XG, g_XG);     cudaGetSymbolAddress((void**)&Ucm, g_Ucm);
    cudaGetSymbolAddress((void**)&X0T, g_X0T);   cudaGetSymbolAddress((void**)&XG1, g_XG1);
    cudaGetSymbolAddress((void**)&G0, g_G0);     cudaGetSymbolAddress((void**)&G1, g_G1);
    cudaGetSymbolAddress((void**)&Rb, g_Rb);     cudaGetSymbolAddress((void**)&Yp, g_Yp);
    cudaGetSymbolAddress((void**)&s0, g_s0);     cudaGetSymbolAddress((void**)&s1, g_s1);
    cudaGetSymbolAddress((void**)&iwTg, g_iwTg); cudaGetSymbolAddress((void**)&Wcomb, g_Wcomb);
    cudaGetSymbolAddress((void**)&bias2, g_bias2);
    cudaGetSymbolAddress((void**)&rs, g_rs);     cudaGetSymbolAddress((void**)&vv, g_vv);
    cudaGetSymbolAddress((void**)&WtgH, g_WtgH); cudaGetSymbolAddress((void**)&WtgL, g_WtgL);
    cudaGetSymbolAddress((void**)&WtuH, g_WtuH); cudaGetSymbolAddress((void**)&WtuL, g_WtuL);

    const long sXG = (long)Nn * KI;
    const long NN = (long)Nn * Nn;
    dim3 tb(32, 8);

    cudaMemcpyAsync(Amats, Lm, NN * sizeof(float), cudaMemcpyDeviceToDevice);
    cudaMemcpyAsync(Amats + 2 * NN, cheb, 3 * NN * sizeof(float), cudaMemcpyDeviceToDevice);

    emb_wsplit<OG><<<dim3(32, 18, 4), 256>>>(emb, gwpool, WtgH, WtgL);
    emb_wsplit<OU><<<dim3(32, 18, 2), 256>>>(emb, uwpool, WtuH, WtuL);
    transpose_batched<<<dim3(32, 32, 1), tb>>>(Lm, 0, Nn, Lt, 0, Nn, Nn, Nn);
    {
        GA a; a.A = Lm; a.lda = Nn; a.sA2 = 0; a.B = Lt; a.ldb = Nn;
        a.C = Amats + NN; a.ldc = Nn; a.K = Nn; a.alpha = 2.0f; a.mI = 1;
        tc(Nn, Nn, 64, 1, a);
    }
    bias_both<<<dim3(2, 32), 256>>>(emb, gbpool, ubpool, bg, bu);

    transpose_batched<<<dim3(4, 3, 1), tb>>>(giw, 0, CIN, iwTg, 0, OG, OG, CIN);
    {
        GA a; a.A = ggw; a.lda = 3 * OG; a.sA2 = 128; a.B = iwTg; a.ldb = OG;
        a.C = Wcomb; a.cSel = 96; a.ldc = KI; a.K = OG;
        tc(OG, CIN, 96, KSUP, a);
    }
    rowsum<<<KSUP * Nn, 256>>>(cheb, rs, Nn);
    vcomp<<<KSUP, OG>>>(ggw, gib, vv);
    mkbias2<<<Nn, OG>>>(rs, vv, ggb, bias2);

    for (int phase = 0; phase < 2; phase++) {
        const int O = phase ? OU : OG;
        if (phase == 0)
            build_ucm<<<dim3(32, 3, Bb), tb>>>(x, state, XG, Ucm);

        if (phase == 0) {
            GA a; a.A = Amats; a.lda = Nn; a.sA2 = NN; a.B = Ucm; a.ldb = Nn;
            a.C = XG + CIN; a.Calt = XG1; a.zc = 2; a.cSel = CIN;
            a.ldc = KI; a.sCb = sXG; a.scatDiv = CIN; a.K = Nn;
            tc(Nn, Bb * CIN, 128, 5, a);
        } else {
            GA a; a.A = XG; a.lda = KI; a.sA2 = 0; a.B = uiw; a.ldb = CIN;
            a.C = nullptr; a.ldc = OU; a.K = CIN; a.bias = uib;
            a.TO = X0T; a.sTOb = (long)OU * Nn;
            tc(Bb * Nn, OU, 64, 1, a);
            GA d; d.A = Amats; d.lda = Nn; d.sA2 = NN; d.B = Ucm; d.ldb = Nn;
            d.C = XG + CIN; d.cSel = CIN; d.ldc = KI; d.sCb = sXG; d.scatDiv = CIN; d.K = Nn;
            tc(Nn, Bb * CIN, 128, 2, d);
            GA c; c.A = Amats + 2 * NN; c.lda = Nn; c.sA2 = NN; c.B = X0T; c.ldb = Nn;
            c.C = XG1; c.cSel = OU; c.ldc = 3 * OU; c.sCb = (long)Nn * 3 * OU;
            c.scatDiv = OU; c.K = Nn;
            tc(Nn, Bb * OU, 128, KSUP, c);
        }
        if (phase == 0) pernode_mma<OG><<<Nn, 256>>>(XG, WtgH, WtgL, bg, G0);
        else            pernode_mma<OU><<<Nn, 256>>>(XG, WtuH, WtuL, bu, G0);

        if (phase == 0) {
            GA a; a.A = XG1; a.lda = KI; a.sA2 = 0; a.B = Wcomb; a.ldb = KI;
            a.C = G1; a.ldc = OG; a.K = KI; a.bias2 = bias2; a.ldb2 = OG;
            tc(Bb * Nn, OG, 128, 1, a);
        } else {
            GA g; g.A = XG1; g.lda = 3 * OU; g.sA2 = 0; g.B = ugw; g.ldb = 3 * OU;
            g.C = G1; g.ldc = OU; g.K = 3 * OU; g.bias = ugb;
            tc(Bb * Nn, OU, 64, 1, g);
        }
        colmean_part<<<dim3(Bb, 8, 2), O>>>(G0, G1, Yp, O);
        if (phase == 0) {
            att_fused<<<dim3(Bb, 2), 128>>>(Yp, ga1w1, ga1w2, ga2w1, ga2w2, s0, s1, OG, OG / 16);
            gate_combine_t<<<dim3(32, 3, Bb), tb>>>(G0, G1, s0, s1, x, state, XG, Ucm, Rb);
        } else {
            att_fused<<<dim3(Bb, 2), 128>>>(Yp, ua1w1, ua1w2, ua2w1, ua2w2, s0, s1, OU, OU / 16);
            final_combine<<<((long)Bb * Nn * DOUT + 255) / 256, 256>>>(G0, G1, s0, s1, Rb, state, out);
        }
    }
}

// round 17
// speedup vs baseline: 1.0917x; 1.0917x over previous
#include <cuda_runtime.h>
#include <cuda_bf16.h>
#include <math.h>
#include <stdint.h>

#define Bb   64
#define Nn   1024
#define DIN  32
#define DOUT 64
#define CIN  96
#define KSUP 3
#define EDm  16
#define OG   128
#define OU   64
#define KI   288

__device__ float g_bg [(size_t)Nn * OG];
__device__ float g_bu [(size_t)Nn * OU];
__device__ float g_Lt [(size_t)Nn * Nn];
__device__ float g_Amats[(size_t)5 * Nn * Nn];   // [L, S2, cheb0, cheb1, cheb2]
__device__ float g_XG [(size_t)Bb * Nn * KI];
__device__ float g_Ucm [(size_t)Bb * CIN * Nn];
__device__ float g_X0T[(size_t)Bb * OG * Nn];
__device__ float g_XG1[(size_t)Bb * Nn * 3 * OG];
__device__ float g_G0 [(size_t)Bb * Nn * OG];
__device__ float g_G1 [(size_t)Bb * Nn * OG];
__device__ float g_Rb [(size_t)Bb * Nn * DOUT];
__device__ float g_Yp [2 * Bb * 8 * OG];
__device__ float g_s0 [Bb];
__device__ float g_s1 [Bb];
__device__ float g_iwTg [CIN * OG];
__device__ float g_Wcomb[OG * KI];
__device__ float g_bias2[Nn * OG];
__device__ float g_rs [KSUP * Nn];
__device__ float g_vv [KSUP * OG];
__device__ uint32_t g_WtgH[(size_t)Nn * OG * (KI / 2)], g_WtgL[(size_t)Nn * OG * (KI / 2)];
__device__ uint32_t g_WtuH[(size_t)Nn * OU * (KI / 2)], g_WtuL[(size_t)Nn * OU * (KI / 2)];

// ---------- mma / ldmatrix helpers ----------
static __device__ __forceinline__ void mma16(float* d, const uint32_t* a,
                                             uint32_t b0, uint32_t b1) {
    asm volatile(
        "mma.sync.aligned.m16n8k16.row.col.f32.bf16.bf16.f32 "
        "{%0,%1,%2,%3}, {%4,%5,%6,%7}, {%8,%9}, {%0,%1,%2,%3};"
        : "+f"(d[0]), "+f"(d[1]), "+f"(d[2]), "+f"(d[3])
        : "r"(a[0]), "r"(a[1]), "r"(a[2]), "r"(a[3]), "r"(b0), "r"(b1));
}
#define LDMX4(r, ad) \
    asm volatile("ldmatrix.sync.aligned.m8n8.x4.shared.b16 {%0,%1,%2,%3}, [%4];" \
        : "=r"((r)[0]), "=r"((r)[1]), "=r"((r)[2]), "=r"((r)[3]) : "r"(ad))
#define LDMX2(r0, r1, ad) \
    asm volatile("ldmatrix.sync.aligned.m8n8.x2.shared.b16 {%0,%1}, [%2];" \
        : "=r"(r0), "=r"(r1) : "r"(ad))

static __device__ __forceinline__ uint32_t packbf(float x, float y) {
    __nv_bfloat162 h = __floats2bfloat162_rn(x, y);
    return *reinterpret_cast<uint32_t*>(&h);
}
static __device__ __forceinline__ void split2(float a, float b, uint32_t& hi, uint32_t& lo) {
    __nv_bfloat16 ha = __float2bfloat16_rn(a), hb = __float2bfloat16_rn(b);
    __nv_bfloat162 p; p.x = ha; p.y = hb;
    hi = *reinterpret_cast<uint32_t*>(&p);
    lo = packbf(a - __bfloat162float(ha), b - __bfloat162float(hb));
}
static __device__ __forceinline__ void split4(float4 v, uint2& hi, uint2& lo) {
    split2(v.x, v.y, hi.x, lo.x);
    split2(v.z, v.w, hi.y, lo.y);
}

#define RSTR 20

// ---------- bf16x3 GEMM (R15 winner) ----------
template <int NT>
__global__ __launch_bounds__(256, 1) void mma_gemm(
    const float* __restrict__ A, int lda, long sA2,
    const float* __restrict__ Bm, int ldb,
    float* __restrict__ C, float* __restrict__ Calt, int zc, long cSel,
    int ldc, long sCb, int scatDiv,
    int K, const float* __restrict__ bias, const float* __restrict__ bias2, int ldb2,
    float alpha, int minusI, float* __restrict__ TO, long sTOb)
{
    constexpr int NTILES = NT / 16;
    constexpr int NB = NT / 32;
    constexpr int AROWS_U32 = 128 * RSTR;
    constexpr int BROWS_U32 = NT * RSTR;
    constexpr int STG = 2 * AROWS_U32 + 2 * BROWS_U32;

    extern __shared__ uint32_t dsm[];

    const int z = blockIdx.z;
    A += (long)z * sA2;
    float* Cbase = (z < zc) ? C + (long)z * cSel : Calt + (long)(z - zc) * cSel;

    const int m0 = blockIdx.y * 128, n0 = blockIdx.x * NT;
    const int tid = threadIdx.x, wid = tid >> 5, lid = tid & 31;
    const int g = lid >> 2, t = lid & 3;
    const int wm = (wid & 3) * 32, wn = (wid >> 2) * (NT / 2);

    const float* Ag = A + (long)m0 * lda;
    const float* Bg = Bm + (long)n0 * ldb;

    float acc[2][NTILES][4];
    #pragma unroll
    for (int i = 0; i < 2; i++)
        #pragma unroll
        for (int j = 0; j < NTILES; j++)
            #pragma unroll
            for (int q = 0; q < 4; q++) acc[i][j][q] = 0.f;

    const int nch = K >> 5;
    float4 pA[4], pB[NB];

    const uint32_t smem0 = (uint32_t)__cvta_generic_to_shared(dsm);
    const uint32_t laneAoff = (((wm + (lid & 15)) * RSTR + ((lid & 16) ? 4 : 0)) << 2);
    const uint32_t laneBoff = (((2 * AROWS_U32) + (wn + (lid & 7)) * RSTR + ((lid & 8) ? 4 : 0)) << 2);

    #pragma unroll
    for (int i = 0; i < 4; i++) {
        int f = i * 256 + tid;
        pA[i] = *(const float4*)(Ag + (long)(f >> 3) * lda + ((f & 7) << 2));
    }
    #pragma unroll
    for (int i = 0; i < NB; i++) {
        int f = i * 256 + tid;
        pB[i] = *(const float4*)(Bg + (long)(f >> 3) * ldb + ((f & 7) << 2));
    }
    {
        uint32_t* Ah = dsm;                 uint32_t* Al = dsm + AROWS_U32;
        uint32_t* Bh = dsm + 2 * AROWS_U32; uint32_t* Bl = Bh + BROWS_U32;
        #pragma unroll
        for (int i = 0; i < 4; i++) {
            int f = i * 256 + tid, row = f >> 3, q = f & 7;
            uint2 hi, lo; split4(pA[i], hi, lo);
            *(uint2*)(Ah + row * RSTR + 2 * q) = hi;
            *(uint2*)(Al + row * RSTR + 2 * q) = lo;
        }
        #pragma unroll
        for (int i = 0; i < NB; i++) {
            int f = i * 256 + tid, row = f >> 3, q = f & 7;
            uint2 hi, lo; split4(pB[i], hi, lo);
            *(uint2*)(Bh + row * RSTR + 2 * q) = hi;
            *(uint2*)(Bl + row * RSTR + 2 * q) = lo;
        }
    }
    __syncthreads();

    for (int c = 0; c < nch; c++) {
        if (c + 1 < nch) {
            const int k0 = (c + 1) << 5;
            #pragma unroll
            for (int i = 0; i < 4; i++) {
                int f = i * 256 + tid;
                pA[i] = *(const float4*)(Ag + (long)(f >> 3) * lda + k0 + ((f & 7) << 2));
            }
            #pragma unroll
            for (int i = 0; i < NB; i++) {
                int f = i * 256 + tid;
                pB[i] = *(const float4*)(Bg + (long)(f >> 3) * ldb + k0 + ((f & 7) << 2));
            }
        }
        {
            const uint32_t stB = smem0 + (c & 1) * (STG << 2);
            const uint32_t aA = stB + laneAoff;
            const uint32_t aB = stB + laneBoff;
            #pragma unroll
            for (int s = 0; s < 2; s++) {
                uint32_t ah[2][4], al[2][4];
                #pragma unroll
                for (int mt = 0; mt < 2; mt++) {
                    uint32_t ad = aA + mt * (16 * RSTR * 4) + s * 32;
                    LDMX4(ah[mt], ad);
                    LDMX4(al[mt], ad + AROWS_U32 * 4);
                }
                #pragma unroll
                for (int nt = 0; nt < NTILES; nt++) {
                    uint32_t bd = aB + nt * (8 * RSTR * 4) + s * 32;
                    uint32_t bh0, bh1, bl0, bl1;
                    LDMX2(bh0, bh1, bd);
                    LDMX2(bl0, bl1, bd + BROWS_U32 * 4);
                    #pragma unroll
                    for (int mt = 0; mt < 2; mt++) {
                        mma16(acc[mt][nt], ah[mt], bh0, bh1);
                        mma16(acc[mt][nt], al[mt], bh0, bh1);
                        mma16(acc[mt][nt], ah[mt], bl0, bl1);
                    }
                }
            }
        }
        if (c + 1 < nch) {
            uint32_t* base = dsm + ((c + 1) & 1) * STG;
            uint32_t* Ah = base;                 uint32_t* Al = base + AROWS_U32;
            uint32_t* Bh = base + 2 * AROWS_U32; uint32_t* Bl = Bh + BROWS_U32;
            #pragma unroll
            for (int i = 0; i < 4; i++) {
                int f = i * 256 + tid, row = f >> 3, q = f & 7;
                uint2 hi, lo; split4(pA[i], hi, lo);
                *(uint2*)(Ah + row * RSTR + 2 * q) = hi;
                *(uint2*)(Al + row * RSTR + 2 * q) = lo;
            }
            #pragma unroll
            for (int i = 0; i < NB; i++) {
                int f = i * 256 + tid, row = f >> 3, q = f & 7;
                uint2 hi, lo; split4(pB[i], hi, lo);
                *(uint2*)(Bh + row * RSTR + 2 * q) = hi;
                *(uint2*)(Bl + row * RSTR + 2 * q) = lo;
            }
            __syncthreads();
        }
    }

    #pragma unroll
    for (int mt = 0; mt < 2; mt++) {
        int r0 = m0 + wm + mt * 16 + g;
        #pragma unroll
        for (int nt = 0; nt < NTILES; nt++) {
            int col = n0 + wn + nt * 8 + t * 2;
            float b0 = 0.f, b1 = 0.f;
            if (bias) { b0 = __ldg(&bias[col]); b1 = __ldg(&bias[col + 1]); }
            float d0 = acc[mt][nt][0] * alpha + b0;
            float d1 = acc[mt][nt][1] * alpha + b1;
            float d2 = acc[mt][nt][2] * alpha + b0;
            float d3 = acc[mt][nt][3] * alpha + b1;
            if (bias2) {
                const float* p0 = bias2 + (long)(r0 & 1023) * ldb2 + col;
                const float* p1 = bias2 + (long)((r0 + 8) & 1023) * ldb2 + col;
                d0 += p0[0]; d1 += p0[1]; d2 += p1[0]; d3 += p1[1];
            }
            if (minusI) {
                if (r0 == col)         d0 -= 1.0f;
                if (r0 == col + 1)     d1 -= 1.0f;
                if (r0 + 8 == col)     d2 -= 1.0f;
                if (r0 + 8 == col + 1) d3 -= 1.0f;
            }
            if (TO) {
                int bb = r0 >> 10, rr = r0 & 1023;
                float* p = TO + (long)bb * sTOb + (long)col * Nn + rr;
                p[0] = d0; p[Nn] = d1; p[8] = d2; p[Nn + 8] = d3;
            } else if (scatDiv) {
                int b = col / scatDiv, cc = col - b * scatDiv;
                float* p = Cbase + (long)b * sCb + (long)r0 * ldc + cc;
                *(float2*)p = make_float2(d0, d1);
                *(float2*)(p + 8L * ldc) = make_float2(d2, d3);
            } else {
                *(float2*)(Cbase + (long)r0 * ldc + col)       = make_float2(d0, d1);
                *(float2*)(Cbase + (long)(r0 + 8) * ldc + col) = make_float2(d2, d3);
            }
        }
    }
}

// ---------- fused emb@pool -> transposed split weights ----------
template <int O>
__global__ __launch_bounds__(256) void emb_wsplit(
    const float* __restrict__ emb, const float* __restrict__ pool,
    uint32_t* __restrict__ WtH, uint32_t* __restrict__ WtL)
{
    __shared__ float es[32][EDm];
    __shared__ float ps[EDm][16][32];
    const int tid = threadIdx.x;
    const int n0 = blockIdx.x * 32;
    const int ki0 = blockIdx.y * 16;
    const int o0 = blockIdx.z * 32;
    const int Ctot = KI * O;
    for (int i = tid; i < 32 * EDm; i += 256)
        es[i >> 4][i & 15] = emb[(n0 + (i >> 4)) * EDm + (i & 15)];
    for (int i = tid; i < EDm * 16 * 32; i += 256) {
        int o = i & 31, kil = (i >> 5) & 15, d = i >> 9;
        ps[d][kil][o] = pool[(long)d * Ctot + (long)(ki0 + kil) * O + o0 + o];
    }
    __syncthreads();
    const int kp = tid & 7, o = tid >> 3;
    float p0[EDm], p1[EDm];
    #pragma unroll
    for (int d = 0; d < EDm; d++) { p0[d] = ps[d][2 * kp][o]; p1[d] = ps[d][2 * kp + 1][o]; }
    const long base = (long)(o0 + o) * (KI / 2) + (ki0 >> 1) + kp;
    for (int n = 0; n < 32; n++) {
        float v0 = 0.f, v1 = 0.f;
        #pragma unroll
        for (int d = 0; d < EDm; d++) { float e = es[n][d]; v0 += e * p0[d]; v1 += e * p1[d]; }
        uint32_t h, l; split2(v0, v1, h, l);
        long off = (long)(n0 + n) * O * (KI / 2) + base;
        WtH[off] = h; WtL[off] = l;
    }
}

// ---------- per-node contraction ----------
template <int O>
__global__ __launch_bounds__(256, 1) void pernode_mma(
    const float* __restrict__ XG, const uint32_t* __restrict__ WtH,
    const uint32_t* __restrict__ WtL, const float* __restrict__ bias,
    float* __restrict__ out)
{
    constexpr int NTILES = O / 32;
    constexpr int AR = 64 * RSTR;
    constexpr int BR = O * RSTR;
    __shared__ uint32_t psm[2 * AR + 2 * BR];

    const int n = blockIdx.x, tid = threadIdx.x, wid = tid >> 5, lid = tid & 31;
    const int g = lid >> 2, t = lid & 3;
    const int wm = (wid & 1) * 32, wn = (wid >> 1) * (O / 4);

    const uint32_t* Hn = WtH + (long)n * O * (KI / 2);
    const uint32_t* Ln = WtL + (long)n * O * (KI / 2);

    float acc[2][NTILES][4];
    #pragma unroll
    for (int i = 0; i < 2; i++)
        #pragma unroll
        for (int j = 0; j < NTILES; j++)
            #pragma unroll
            for (int q = 0; q < 4; q++) acc[i][j][q] = 0.f;

    const uint32_t smem0 = (uint32_t)__cvta_generic_to_shared(psm);
    const uint32_t laneAoff = (((wm + (lid & 15)) * RSTR + ((lid & 16) ? 4 : 0)) << 2);
    const uint32_t laneBoff = (((2 * AR) + (wn + (lid & 7)) * RSTR + ((lid & 8) ? 4 : 0)) << 2);

    uint32_t* Ah = psm;          uint32_t* Al = psm + AR;
    uint32_t* Bh = psm + 2 * AR; uint32_t* Bl = Bh + BR;

    for (int c = 0; c < KI / 32; c++) {
        const int k0 = c << 5;
        if (c) __syncthreads();
        #pragma unroll
        for (int i = 0; i < 2; i++) {
            int f = i * 256 + tid, row = f >> 3, q = f & 7;
            float4 v = *(const float4*)(XG + ((long)row * Nn + n) * KI + k0 + (q << 2));
            uint2 hi, lo; split4(v, hi, lo);
            *(uint2*)(Ah + row * RSTR + 2 * q) = hi;
            *(uint2*)(Al + row * RSTR + 2 * q) = lo;
        }
        #pragma unroll
        for (int i = 0; i < O / 64; i++) {
            int f = i * 256 + tid, row = f >> 2, qc = (f & 3) << 2;
            *(uint4*)(Bh + row * RSTR + qc) = *(const uint4*)(Hn + (long)row * (KI / 2) + (k0 >> 1) + qc);
            *(uint4*)(Bl + row * RSTR + qc) = *(const uint4*)(Ln + (long)row * (KI / 2) + (k0 >> 1) + qc);
        }
        __syncthreads();

        #pragma unroll
        for (int s = 0; s < 2; s++) {
            uint32_t ah[2][4], al[2][4];
            #pragma unroll
            for (int mt = 0; mt < 2; mt++) {
                uint32_t ad = smem0 + laneAoff + mt * (16 * RSTR * 4) + s * 32;
                LDMX4(ah[mt], ad);
                LDMX4(al[mt], ad + AR * 4);
            }
            #pragma unroll
            for (int nt = 0; nt < NTILES; nt++) {
                uint32_t bd = smem0 + laneBoff + nt * (8 * RSTR * 4) + s * 32;
                uint32_t bh0, bh1, bl0, bl1;
                LDMX2(bh0, bh1, bd);
                LDMX2(bl0, bl1, bd + BR * 4);
                #pragma unroll
                for (int mt = 0; mt < 2; mt++) {
                    mma16(acc[mt][nt], ah[mt], bh0, bh1);
                    mma16(acc[mt][nt], al[mt], bh0, bh1);
                    mma16(acc[mt][nt], ah[mt], bl0, bl1);
                }
            }
        }
    }

    #pragma unroll
    for (int mt = 0; mt < 2; mt++) {
        int b = wm + mt * 16 + g;
        #pragma unroll
        for (int nt = 0; nt < NTILES; nt++) {
            int col = wn + nt * 8 + t * 2;
            float b0 = bias[(long)n * O + col], b1 = bias[(long)n * O + col + 1];
            *(float2*)(out + ((long)b * Nn + n) * O + col) =
                make_float2(acc[mt][nt][0] + b0, acc[mt][nt][1] + b1);
            *(float2*)(out + ((long)(b + 8) * Nn + n) * O + col) =
                make_float2(acc[mt][nt][2] + b0, acc[mt][nt][3] + b1);
        }
    }
}

// ---------- small kernels ----------
static __device__ __forceinline__ float lrelu(float v) { return v >= 0.0f ? v : 0.01f * v; }
static __device__ __forceinline__ float sigmoidf(float v) { return 1.0f / (1.0f + expf(-v)); }

__global__ void bias_both(const float* __restrict__ emb,
                          const float* __restrict__ gpool, const float* __restrict__ upool,
                          float* __restrict__ bgo, float* __restrict__ buo)
{
    __shared__ float esm[32][EDm];
    const int tid = threadIdx.x;
    const int which = blockIdx.x;
    const int n0 = blockIdx.y * 32;
    const int C = which ? OU : OG;
    const float* pool = which ? upool : gpool;
    float* out = which ? buo : bgo;
    for (int i = tid; i < 32 * EDm; i += 256)
        esm[i >> 4][i & 15] = emb[(n0 + (i >> 4)) * EDm + (i & 15)];
    __syncthreads();
    if (tid >= C) return;
    float p[EDm];
    #pragma unroll
    for (int d = 0; d < EDm; d++) p[d] = pool[(long)d * C + tid];
    #pragma unroll 4
    for (int r = 0; r < 32; r++) {
        float acc = 0.f;
        #pragma unroll
        for (int d = 0; d < EDm; d++) acc += esm[r][d] * p[d];
        out[(long)(n0 + r) * C + tid] = acc;
    }
}

__global__ void transpose_batched(const float* __restrict__ in, long s_in, int ld_in,
                                  float* __restrict__ out, long s_out, int ld_out,
                                  int R, int Cc)
{
    __shared__ float tsm[32][33];
    in  += (long)blockIdx.z * s_in;
    out += (long)blockIdx.z * s_out;
    int r0 = blockIdx.x * 32, c0 = blockIdx.y * 32;
    int c = c0 + threadIdx.x;
    #pragma unroll
    for (int i = 0; i < 32; i += 8) {
        int rr = r0 + threadIdx.y + i;
        if (rr < R && c < Cc) tsm[threadIdx.y + i][threadIdx.x] = in[(long)rr * ld_in + c];
    }
    __syncthreads();
    int rr = r0 + threadIdx.x;
    #pragma unroll
    for (int i = 0; i < 32; i += 8) {
        int cc = c0 + threadIdx.y + i;
        if (cc < Cc && rr < R) out[(long)cc * ld_out + rr] = tsm[threadIdx.x][threadIdx.y + i];
    }
}

__global__ void build_ucm(const float* __restrict__ x, const float* __restrict__ st,
                          float* __restrict__ XG, float* __restrict__ Ucm)
{
    __shared__ float tsm[32][33];
    const int n0 = blockIdx.x * 32, c0 = blockIdx.y * 32, b = blockIdx.z;
    const int c = threadIdx.x;
    #pragma unroll
    for (int i = 0; i < 32; i += 8) {
        int n = n0 + threadIdx.y + i;
        long bn = (long)b * Nn + n;
        int gc = c0 + c;
        float v = (gc < DIN) ? x[bn * DIN + gc] : st[bn * DOUT + (gc - DIN)];
        tsm[threadIdx.y + i][c] = v;
        XG[bn * KI + gc] = v;
    }
    __syncthreads();
    const int n = n0 + threadIdx.x;
    #pragma unroll
    for (int i = 0; i < 32; i += 8) {
        int gc = c0 + threadIdx.y + i;
        Ucm[((long)b * CIN + gc) * Nn + n] = tsm[threadIdx.x][threadIdx.y + i];
    }
}

__global__ void gate_combine_t(const float* __restrict__ G0, const float* __restrict__ G1,
                               const float* __restrict__ s0, const float* __restrict__ s1,
                               const float* __restrict__ x, const float* __restrict__ st,
                               float* __restrict__ XG, float* __restrict__ Ucm,
                               float* __restrict__ Rb)
{
    __shared__ float tsm[32][33];
    const int n0 = blockIdx.x * 32, c0 = blockIdx.y * 32, b = blockIdx.z;
    const int c = threadIdx.x;
    const float a0 = s0[b], a1 = s1[b];
    #pragma unroll
    for (int i = 0; i < 32; i += 8) {
        int n = n0 + threadIdx.y + i;
        long bn = (long)b * Nn + n;
        int gc = c0 + c;
        float v;
        if (gc < DIN) {
            v = x[bn * DIN + gc];
        } else {
            int o = gc - DIN;
            float zi = lrelu(G0[bn * OG + o]) * a0 + lrelu(G1[bn * OG + o]) * a1;
            float ri = lrelu(G0[bn * OG + DOUT + o]) * a0 + lrelu(G1[bn * OG + DOUT + o]) * a1;
            Rb[bn * DOUT + o] = sigmoidf(ri);
            v = sigmoidf(zi) * st[bn * DOUT + o];
        }
        tsm[threadIdx.y + i][c] = v;
        XG[bn * KI + gc] = v;
    }
    __syncthreads();
    const int n = n0 + threadIdx.x;
    #pragma unroll
    for (int i = 0; i < 32; i += 8) {
        int gc = c0 + threadIdx.y + i;
        Ucm[((long)b * CIN + gc) * Nn + n] = tsm[threadIdx.x][threadIdx.y + i];
    }
}

__global__ void rowsum(const float* __restrict__ M, float* __restrict__ rs, int ncols)
{
    __shared__ float sm[256];
    const float* p = M + (long)blockIdx.x * ncols;
    float s = 0.f;
    for (int i = threadIdx.x; i < ncols; i += 256) s += p[i];
    sm[threadIdx.x] = s;
    __syncthreads();
    for (int o = 128; o; o >>= 1) {
        if (threadIdx.x < o) sm[threadIdx.x] += sm[threadIdx.x + o];
        __syncthreads();
    }
    if (!threadIdx.x) rs[blockIdx.x] = sm[0];
}

__global__ void vcomp(const float* __restrict__ gw, const float* __restrict__ ib,
                      float* __restrict__ vv)
{
    int k = blockIdx.x, o = threadIdx.x;
    float s = 0.f;
    for (int j = 0; j < OG; j++) s += gw[(long)o * (3 * OG) + k * OG + j] * ib[j];
    vv[k * OG + o] = s;
}

__global__ void mkbias2(const float* __restrict__ rs, const float* __restrict__ vv,
                        const float* __restrict__ gb, float* __restrict__ b2)
{
    int n = blockIdx.x, o = threadIdx.x;
    float s = gb[o];
    #pragma unroll
    for (int k = 0; k < KSUP; k++) s += rs[k * Nn + n] * vv[k * OG + o];
    b2[(long)n * OG + o] = s;
}

__global__ void colmean_part(const float* __restrict__ G0, const float* __restrict__ G1,
                             float* __restrict__ Yp, int C)
{
    const int b = blockIdx.x, ch = blockIdx.y, which = blockIdx.z;
    const int c = threadIdx.x;
    const float* p = (which ? G1 : G0) + ((long)b * Nn + ch * 128) * C + c;
    float a0 = 0.f, a1 = 0.f, a2 = 0.f, a3 = 0.f;
    #pragma unroll 4
    for (int n = 0; n < 128; n += 4) {
        a0 += lrelu(p[(long)n * C]);       a1 += lrelu(p[(long)(n + 1) * C]);
        a2 += lrelu(p[(long)(n + 2) * C]); a3 += lrelu(p[(long)(n + 3) * C]);
    }
    Yp[((long)(which * Bb + b) * 8 + ch) * C + c] = (a0 + a1) + (a2 + a3);
}

__global__ void att_fused(const float* __restrict__ Yp,
                          const float* __restrict__ w1a, const float* __restrict__ w2a,
                          const float* __restrict__ w1b, const float* __restrict__ w2b,
                          float* __restrict__ sa, float* __restrict__ sb, int C, int H)
{
    __shared__ float Y[OG];
    const int b = blockIdx.x, which = blockIdx.y;
    const int tid = threadIdx.x;
    if (tid < C) {
        const float* p = Yp + ((long)(which * Bb + b) * 8) * C + tid;
        float s = 0.f;
        #pragma unroll
        for (int ch = 0; ch < 8; ch++) s += p[ch * C];
        Y[tid] = s * (1.0f / (float)Nn);
    }
    __syncthreads();
    const float* w1 = which ? w1b : w1a;
    const float* w2 = which ? w2b : w2a;
    float h = 0.f;
    if (tid < H) {
        float acc = 0.f;
        for (int cc = 0; cc < C; cc++) acc += Y[cc] * w1[tid * C + cc];
        h = fmaxf(acc, 0.f) * w2[tid];
    }
    if (tid < 32) {
        #pragma unroll
        for (int off = 16; off; off >>= 1) h += __shfl_down_sync(0xffffffffu, h, off);
        if (tid == 0) (which ? sb : sa)[b] = sigmoidf(h);
    }
}

__global__ void final_combine(const float* __restrict__ G0u, const float* __restrict__ G1u,
                              const float* __restrict__ t0, const float* __restrict__ t1,
                              const float* __restrict__ Rb, const float* __restrict__ st,
                              float* __restrict__ out)
{
    long idx = (long)blockIdx.x * blockDim.x + threadIdx.x;
    if (idx >= (long)Bb * Nn * DOUT) return;
    long bn = idx / DOUT;
    int b = (int)(bn >> 10);
    float hc = tanhf(lrelu(G0u[idx]) * t0[b] + lrelu(G1u[idx]) * t1[b]);
    float r = Rb[idx];
    out[idx] = r * st[idx] + (1.0f - r) * hc;
}

// ---------- host ----------
static inline int gemm_smem(int NT) { return 2 * (2 * 128 * RSTR + 2 * NT * RSTR) * 4; }

struct GA {
    const float* A; int lda; long sA2;
    const float* B; int ldb;
    float* C; float* Calt = nullptr; int zc = 99; long cSel = 0;
    int ldc; long sCb = 0; int scatDiv = 0;
    int K; const float* bias = nullptr; const float* bias2 = nullptr; int ldb2 = 0;
    float alpha = 1.0f; int mI = 0;
    float* TO = nullptr; long sTOb = 0;
};
static inline void tc(int M, int N, int NT, int gz, const GA& a)
{
    dim3 grid(N / NT, M / 128, gz);
    int sm = gemm_smem(NT);
#define LNCH(T) \
    cudaFuncSetAttribute(mma_gemm<T>, cudaFuncAttributeMaxDynamicSharedMemorySize, sm); \
    mma_gemm<T><<<grid, 256, sm>>>(a.A, a.lda, a.sA2, a.B, a.ldb, \
        a.C, a.Calt, a.zc, a.cSel, a.ldc, a.sCb, a.scatDiv, \
        a.K, a.bias, a.bias2, a.ldb2, a.alpha, a.mI, a.TO, a.sTOb)
    switch (NT) {
    case 128: { LNCH(128); break; }
    case 96:  { LNCH(96);  break; }
    default:  { LNCH(64);  break; }
    }
#undef LNCH
}

extern "C" void kernel_launch(void* const* d_in, const int* in_sizes, int n_in,
                              void* d_out, int out_size)
{
    const float* x     = (const float*)d_in[0];
    const float* state = (const float*)d_in[1];
    const float* emb   = (const float*)d_in[2];
    const float* Lm    = (const float*)d_in[3];
    const float* cheb  = (const float*)d_in[4];
    const float* gwpool = (const float*)d_in[5];
    const float* gbpool = (const float*)d_in[6];
    const float* giw = (const float*)d_in[7];
    const float* gib = (const float*)d_in[8];
    const float* ggw = (const float*)d_in[9];
    const float* ggb = (const float*)d_in[10];
    const float* ga1w1 = (const float*)d_in[11];
    const float* ga1w2 = (const float*)d_in[12];
    const float* ga2w1 = (const float*)d_in[13];
    const float* ga2w2 = (const float*)d_in[14];
    const float* uwpool = (const float*)d_in[15];
    const float* ubpool = (const float*)d_in[16];
    const float* uiw = (const float*)d_in[17];
    const float* uib = (const float*)d_in[18];
    const float* ugw = (const float*)d_in[19];
    const float* ugb = (const float*)d_in[20];
    const float* ua1w1 = (const float*)d_in[21];
    const float* ua1w2 = (const float*)d_in[22];
    const float* ua2w1 = (const float*)d_in[23];
    const float* ua2w2 = (const float*)d_in[24];
    float* out = (float*)d_out;

    float *bg, *bu, *Lt, *Amats, *XG, *Ucm, *X0T, *XG1;
    float *G0, *G1, *Rb, *Yp, *s0, *s1;
    float *iwTg, *Wcomb, *bias2, *rs, *vv;
    uint32_t *WtgH, *WtgL, *WtuH, *WtuL;
    cudaGetSymbolAddress((void**)&bg, g_bg);     cudaGetSymbolAddress((void**)&bu, g_bu);
    cudaGetSymbolAddress((void**)&Lt, g_Lt);     cudaGetSymbolAddress((void**)&Amats, g_Amats);
    cudaGetSymbolAddress((void**)&XG, g_XG);     cudaGetSymbolAddress((void**)&Ucm, g_Ucm);
    cudaGetSymbolAddress((void**)&X0T, g_X0T);   cudaGetSymbolAddress((void**)&XG1, g_XG1);
    cudaGetSymbolAddress((void**)&G0, g_G0);     cudaGetSymbolAddress((void**)&G1, g_G1);
    cudaGetSymbolAddress((void**)&Rb, g_Rb);     cudaGetSymbolAddress((void**)&Yp, g_Yp);
    cudaGetSymbolAddress((void**)&s0, g_s0);     cudaGetSymbolAddress((void**)&s1, g_s1);
    cudaGetSymbolAddress((void**)&iwTg, g_iwTg); cudaGetSymbolAddress((void**)&Wcomb, g_Wcomb);
    cudaGetSymbolAddress((void**)&bias2, g_bias2);
    cudaGetSymbolAddress((void**)&rs, g_rs);     cudaGetSymbolAddress((void**)&vv, g_vv);
    cudaGetSymbolAddress((void**)&WtgH, g_WtgH); cudaGetSymbolAddress((void**)&WtgL, g_WtgL);
    cudaGetSymbolAddress((void**)&WtuH, g_WtuH); cudaGetSymbolAddress((void**)&WtuL, g_WtuL);

    const long sXG = (long)Nn * KI;
    const long NN = (long)Nn * Nn;
    dim3 tb(32, 8);

    cudaMemcpyAsync(Amats, Lm, NN * sizeof(float), cudaMemcpyDeviceToDevice);
    cudaMemcpyAsync(Amats + 2 * NN, cheb, 3 * NN * sizeof(float), cudaMemcpyDeviceToDevice);

    emb_wsplit<OG><<<dim3(32, 18, 4), 256>>>(emb, gwpool, WtgH, WtgL);
    emb_wsplit<OU><<<dim3(32, 18, 2), 256>>>(emb, uwpool, WtuH, WtuL);
    transpose_batched<<<dim3(32, 32, 1), tb>>>(Lm, 0, Nn, Lt, 0, Nn, Nn, Nn);
    {
        GA a; a.A = Lm; a.lda = Nn; a.sA2 = 0; a.B = Lt; a.ldb = Nn;
        a.C = Amats + NN; a.ldc = Nn; a.K = Nn; a.alpha = 2.0f; a.mI = 1;
        tc(Nn, Nn, 64, 1, a);
    }
    bias_both<<<dim3(2, 32), 256>>>(emb, gbpool, ubpool, bg, bu);

    transpose_batched<<<dim3(4, 3, 1), tb>>>(giw, 0, CIN, iwTg, 0, OG, OG, CIN);
    {
        GA a; a.A = ggw; a.lda = 3 * OG; a.sA2 = 128; a.B = iwTg; a.ldb = OG;
        a.C = Wcomb; a.cSel = 96; a.ldc = KI; a.K = OG;
        tc(OG, CIN, 96, KSUP, a);
    }
    rowsum<<<KSUP * Nn, 256>>>(cheb, rs, Nn);
    vcomp<<<KSUP, OG>>>(ggw, gib, vv);
    mkbias2<<<Nn, OG>>>(rs, vv, ggb, bias2);

    for (int phase = 0; phase < 2; phase++) {
        const int O = phase ? OU : OG;
        if (phase == 0)
            build_ucm<<<dim3(32, 3, Bb), tb>>>(x, state, XG, Ucm);

        if (phase == 0) {
            GA a; a.A = Amats; a.lda = Nn; a.sA2 = NN; a.B = Ucm; a.ldb = Nn;
            a.C = XG + CIN; a.Calt = XG1; a.zc = 2; a.cSel = CIN;
            a.ldc = KI; a.sCb = sXG; a.scatDiv = CIN; a.K = Nn;
            tc(Nn, Bb * CIN, 128, 5, a);
        } else {
            GA a; a.A = XG; a.lda = KI; a.sA2 = 0; a.B = uiw; a.ldb = CIN;
            a.C = nullptr; a.ldc = OU; a.K = CIN; a.bias = uib;
            a.TO = X0T; a.sTOb = (long)OU * Nn;
            tc(Bb * Nn, OU, 64, 1, a);
            GA d; d.A = Amats; d.lda = Nn; d.sA2 = NN; d.B = Ucm; d.ldb = Nn;
            d.C = XG + CIN; d.cSel = CIN; d.ldc = KI; d.sCb = sXG; d.scatDiv = CIN; d.K = Nn;
            tc(Nn, Bb * CIN, 128, 2, d);
            GA c; c.A = Amats + 2 * NN; c.lda = Nn; c.sA2 = NN; c.B = X0T; c.ldb = Nn;
            c.C = XG1; c.cSel = OU; c.ldc = 3 * OU; c.sCb = (long)Nn * 3 * OU;
            c.scatDiv = OU; c.K = Nn;
            tc(Nn, Bb * OU, 128, KSUP, c);
        }
        if (phase == 0) pernode_mma<OG><<<Nn, 256>>>(XG, WtgH, WtgL, bg, G0);
        else            pernode_mma<OU><<<Nn, 256>>>(XG, WtuH, WtuL, bu, G0);

        if (phase == 0) {
            GA a; a.A = XG1; a.lda = KI; a.sA2 = 0; a.B = Wcomb; a.ldb = KI;
            a.C = G1; a.ldc = OG; a.K = KI; a.bias2 = bias2; a.ldb2 = OG;
            tc(Bb * Nn, OG, 128, 1, a);
        } else {
            GA g; g.A = XG1; g.lda = 3 * OU; g.sA2 = 0; g.B = ugw; g.ldb = 3 * OU;
            g.C = G1; g.ldc = OU; g.K = 3 * OU; g.bias = ugb;
            tc(Bb * Nn, OU, 64, 1, g);
        }
        colmean_part<<<dim3(Bb, 8, 2), O>>>(G0, G1, Yp, O);
        if (phase == 0) {
            att_fused<<<dim3(Bb, 2), 128>>>(Yp, ga1w1, ga1w2, ga2w1, ga2w2, s0, s1, OG, OG / 16);
            gate_combine_t<<<dim3(32, 3, Bb), tb>>>(G0, G1, s0, s1, x, state, XG, Ucm, Rb);
        } else {
            att_fused<<<dim3(Bb, 2), 128>>>(Yp, ua1w1, ua1w2, ua2w1, ua2w2, s0, s1, OU, OU / 16);
            final_combine<<<((long)Bb * Nn * DOUT + 255) / 256, 256>>>(G0, G1, s0, s1, Rb, state, out);
        }
    }
}